// round 17
// baseline (speedup 1.0000x reference)
#include <cuda_runtime.h>
#include <cuda_bf16.h>
#include <math_constants.h>
#include <stdint.h>

#define NROWS 16384
#define DIMS  256
#define NEMB  8192

// Output layout (float32, reference return order, flattened+concatenated)
#define OFF_Q    0
#define OFF_DIFF 4194304
#define OFF_IND  4194305
#define OFF_EMB  4210689
#define OFF_NCS  6307841
#define OFF_AVG  6316033

// swizzled plane layout: row r (0..127 for A, 0..63 for B), 16B chunk c (0..31)
#define PLANE_ADDR(r, c) ((r) * 512 + (((c) >> 3) << 7) + ((((c) & 7) ^ ((r) & 7)) << 4))

// Scratch (no cudaMalloc allowed). g_zhi/g_ehi hold PRE-SWIZZLED tile layouts
// so cp.async.bulk can stage them linearly. g_enorm carries a uniform +512
// offset (argmin/rescore invariant). g_avgT accumulates 0.01*segment-sum in
// TRANSPOSED [code][dim] layout so the scatter can use red.v4.f32.
__device__ float g_enorm[NEMB];
__device__ int   g_count[NEMB];
__device__ float g_n;
__device__ int   g_done;
__device__ __align__(128) __nv_bfloat16 g_zhi[NROWS * DIMS];  // [blk128][plane 64KB]
__device__ __align__(128) __nv_bfloat16 g_ehi[NEMB * DIMS];   // [tile64][plane 32KB]
__device__ float g_eT[NEMB * DIMS];                            // [code][k] fp32 linear
__device__ __align__(16) float g_avgT[NEMB * DIMS];            // [code][dim] scatter

// ---------------------------------------------------------------------------
// PTX helpers — baseline sm_80/sm_90 features only (target compute_103, no 'a').
// ---------------------------------------------------------------------------
__device__ __forceinline__ uint32_t smem_u32(const void* p) {
    uint32_t a;
    asm("{ .reg .u64 t; cvta.to.shared.u64 t, %1; cvt.u32.u64 %0, t; }" : "=r"(a) : "l"(p));
    return a;
}
__device__ __forceinline__ void bar_sync(int id) {
    asm volatile("bar.sync %0, 256;" :: "r"(id) : "memory");
}
__device__ __forceinline__ void mbar_init(uint32_t a, uint32_t cnt) {
    asm volatile("mbarrier.init.shared.b64 [%0], %1;" :: "r"(a), "r"(cnt) : "memory");
}
__device__ __forceinline__ void mbar_expect_tx(uint32_t a, uint32_t bytes) {
    asm volatile("mbarrier.arrive.expect_tx.shared.b64 _, [%0], %1;"
                 :: "r"(a), "r"(bytes) : "memory");
}
__device__ __forceinline__ void bulk_g2s(uint32_t dst, const void* src,
                                         uint32_t bytes, uint32_t mbar) {
    asm volatile("cp.async.bulk.shared::cta.global.mbarrier::complete_tx::bytes "
                 "[%0], [%1], %2, [%3];"
                 :: "r"(dst), "l"(src), "r"(bytes), "r"(mbar) : "memory");
}
__device__ __forceinline__ void red_add_v4(float* p, float4 v) {
    asm volatile("red.global.add.v4.f32 [%0], {%1, %2, %3, %4};"
                 :: "l"(p), "f"(v.x), "f"(v.y), "f"(v.z), "f"(v.w) : "memory");
}
#define MBAR_WAIT(a, p) do {                                                     \
    uint32_t _m = (a), _p = (p), _d;                                             \
    asm volatile("{\n\t.reg .pred q;\n\t"                                        \
        "mbarrier.try_wait.parity.acquire.cta.shared::cta.b64 q, [%1], %2;\n\t"  \
        "selp.b32 %0, 1, 0, q;\n\t}" : "=r"(_d) : "r"(_m), "r"(_p) : "memory");  \
    if (!_d) {                                                                   \
        asm volatile("{\n\t.reg .pred Q;\n\tWL_%=:\n\t"                          \
            "mbarrier.try_wait.parity.acquire.cta.shared::cta.b64 Q, [%0], %1, 0x989680;\n\t" \
            "@Q bra.uni WD_%=;\n\tbra.uni WL_%=;\n\tWD_%=:\n\t}"                 \
            :: "r"(_m), "r"(_p) : "memory");                                     \
    }                                                                            \
} while (0)

__device__ __forceinline__ void ldsm_x4(uint32_t* r, uint32_t a) {
    asm volatile("ldmatrix.sync.aligned.m8n8.x4.shared.b16 {%0,%1,%2,%3}, [%4];"
                 : "=r"(r[0]), "=r"(r[1]), "=r"(r[2]), "=r"(r[3]) : "r"(a));
}
__device__ __forceinline__ void mma16816(float* d, const uint32_t* a, const uint32_t* b) {
    asm volatile("mma.sync.aligned.m16n8k16.row.col.f32.bf16.bf16.f32 "
                 "{%0,%1,%2,%3}, {%4,%5,%6,%7}, {%8,%9}, {%0,%1,%2,%3};"
                 : "+f"(d[0]), "+f"(d[1]), "+f"(d[2]), "+f"(d[3])
                 : "r"(a[0]), "r"(a[1]), "r"(a[2]), "r"(a[3]), "r"(b[0]), "r"(b[1]));
}

// pack positive float distance with 7-bit local code in low mantissa bits
__device__ __forceinline__ float pack7(float d, uint32_t code) {
    return __uint_as_float((__float_as_uint(d) & 0xFFFFFF80u) | code);
}

// merge two ascending pairs (a0<=a1),(b0<=b1) -> smallest two (branch-free)
__device__ __forceinline__ void p2_merge(float& a0, float& a1, float b0, float b1) {
    float lo = fminf(a0, b0);
    a1 = fminf(fmaxf(a0, b0), fminf(a1, b1));
    a0 = lo;
}

// sorted top-4 insert (ascending); common case = 1 compare
__device__ __forceinline__ void t4_insert(float (&v)[4], int (&j)[4], float d, int c) {
    if (d < v[3]) {
        if (d < v[1]) {
            v[3] = v[2]; j[3] = j[2]; v[2] = v[1]; j[2] = j[1];
            if (d < v[0]) { v[1] = v[0]; j[1] = j[0]; v[0] = d; j[0] = c; }
            else          { v[1] = d; j[1] = c; }
        } else {
            if (d < v[2]) { v[3] = v[2]; j[3] = j[2]; v[2] = d; j[2] = c; }
            else          { v[3] = d; j[3] = c; }
        }
    }
}

// ---------------------------------------------------------------------------
// A: fused prep. Blocks [0, 16384): z conversion + scratch init.
//    Blocks [16384, 18432): E transpose (fp32 + swizzled bf16) + enorm.
//    Block shape (32, 8) = 256 threads for both roles.
// ---------------------------------------------------------------------------
#define CONV_BLOCKS 16384
#define PREP_BLOCKS 2048

__global__ void k_prep_all(const float* __restrict__ z,
                           const float* __restrict__ E,
                           float* __restrict__ out) {
    const int tx = threadIdx.x, ty = threadIdx.y;
    const int t = ty * 32 + tx;
    if (blockIdx.x < CONV_BLOCKS) {
        int i = blockIdx.x * 256 + t;
        int row = i >> 8, k = i & 255;
        int blk = row >> 7, r = row & 127, c = k >> 3;
        uint32_t off = (uint32_t)blk * 65536 + PLANE_ADDR(r, c) + (k & 7) * 2;
        *(__nv_bfloat16*)((char*)g_zhi + off) = __float2bfloat16(z[i]);
        if (i < DIMS * NEMB) g_avgT[i] = 0.0f;
        if (i < NEMB) { g_count[i] = 0; g_enorm[i] = 512.0f; }
        if (i == 0) { g_n = 0.0f; g_done = 0; out[OFF_DIFF] = 0.0f; }
        return;
    }
    __shared__ float tbuf[32][33];
    const int pb = blockIdx.x - CONV_BLOCKS;      // 256 j-tiles x 8 k-tiles
    const int j0 = (pb & 255) * 32, k0 = (pb >> 8) * 32;
#pragma unroll
    for (int s = 0; s < 32; s += 8)
        tbuf[ty + s][tx] = E[(size_t)(k0 + ty + s) * NEMB + j0 + tx];
    __syncthreads();
#pragma unroll
    for (int s = 0; s < 32; s += 8) {
        float x = tbuf[tx][ty + s];
        int j = j0 + ty + s, k = k0 + tx;
        g_eT[(size_t)j * DIMS + k] = x;
        uint32_t off = (uint32_t)(j >> 6) * 32768 + PLANE_ADDR(j & 63, k >> 3) + (k & 7) * 2;
        *(__nv_bfloat16*)((char*)g_ehi + off) = __float2bfloat16(x);
        float p = x * x;
#pragma unroll
        for (int w = 16; w; w >>= 1) p += __shfl_xor_sync(0xffffffffu, p, w);
        if (tx == 0) atomicAdd(&g_enorm[j], p);
    }
}

// ---------------------------------------------------------------------------
// C: split-barrier halves, cp.async.bulk staging, packed min-2 epilogue,
//    register top-4, fused gather with red.v4 scatter, last-CTA ncs/n/diff.
// ---------------------------------------------------------------------------
#define SM_A     0
#define SM_B     65536       // + (half*2+buf)*32768
#define SM_RED   196608      // + (half*2+buf)*5120 ; entry rl*5 + wn*2 + pr (float2)
#define SM_CAND  217088      // 256 x float4 (half1 pv/pj), then final int4, then tail
#define SM_MBAR  221184      // A @ +0; B @ +8 + (half*2+buf)*8
#define SMEM_TOTAL 221696

__global__ __launch_bounds__(512, 1) void k_argmin_mma(
    const float* __restrict__ z, const float* __restrict__ cs,
    float* __restrict__ out)
{
    extern __shared__ char smem[];
    const uint32_t sb = smem_u32(smem);
    const int tid = threadIdx.x, wid = tid >> 5, l = tid & 31;
    const int half = wid >> 3, hw = wid & 7, htid = tid & 255;
    const int wm = hw >> 1, wn = hw & 1;
    const int row0 = blockIdx.x * 128;

    if (tid == 0) {
        mbar_init(sb + SM_MBAR, 1);
#pragma unroll
        for (int b = 0; b < 4; b++) mbar_init(sb + SM_MBAR + 8 + b * 8, 1);
    }
    __syncthreads();

    // stage A (64KB, this CTA's 128-row block) and B tile 0 of each half
    if (tid == 0) {
        mbar_expect_tx(sb + SM_MBAR, 65536);
        bulk_g2s(sb + SM_A, (const char*)g_zhi + (size_t)blockIdx.x * 65536,
                 65536, sb + SM_MBAR);
    }
    if (htid == 0) {
        uint32_t mb = sb + SM_MBAR + 8 + (uint32_t)(half * 2) * 8;
        mbar_expect_tx(mb, 32768);
        bulk_g2s(sb + SM_B + (uint32_t)(half * 2) * 32768,
                 (const char*)g_ehi + (size_t)half * 32768, 32768, mb);
    }

    // persistent per-row top-4 (threads htid<128 of each half, row = htid)
    float pv[4] = {CUDART_INF_F, CUDART_INF_F, CUDART_INF_F, CUDART_INF_F};
    int   pj[4] = {0, 0, 0, 0};

    // fragment lane addressing
    const int arow = wm * 32 + (l & 15);
    const int acd  = l >> 4;
    const int brow = wn * 32 + ((l >> 4) << 3) + (l & 7);
    const int bcd  = (l >> 3) & 1;
    const int lc0  = wn * 32 + 2 * (l & 3);

    uint32_t aoff[4], boff[4];
#pragma unroll
    for (int j = 0; j < 4; j++) {
        aoff[j] = (uint32_t)(((2 * j + acd) ^ (arow & 7)) << 4);
        boff[j] = (uint32_t)(((2 * j + bcd) ^ (brow & 7)) << 4);
    }
    const uint32_t abase  = sb + SM_A + arow * 512;
    const uint32_t bbase0 = sb + SM_B + (uint32_t)(half * 2) * 32768 + brow * 512;
    const uint32_t redb   = sb + SM_RED + (uint32_t)(half * 2) * 5120;

    MBAR_WAIT(sb + SM_MBAR, 0);   // A resident

    for (int q = 0; q < 64; q++) {
        const int buf = q & 1;
        bar_sync(half + 1);   // all half-warps done with epoch q-1 (reads+RED)

        // prefetch next tile (single bulk op; buffer free per the barrier)
        if (q + 1 < 64 && htid == 0) {
            const int nb = (q + 1) & 1;
            uint32_t mb = sb + SM_MBAR + 8 + (uint32_t)(half * 2 + nb) * 8;
            mbar_expect_tx(mb, 32768);
            bulk_g2s(sb + SM_B + (uint32_t)(half * 2 + nb) * 32768,
                     (const char*)g_ehi + (size_t)(2 * (q + 1) + half) * 32768,
                     32768, mb);
        }

        // merge previous tile's warp pair-lists (overlaps other warps' MMA)
        if (q > 0 && htid < 128) {
            const float2* src = (const float2*)(smem + (redb - sb) + ((q - 1) & 1) * 5120)
                                + htid * 5;
            float2 a = src[0], b = src[1], c = src[2], d = src[3];
            p2_merge(a.x, a.y, b.x, b.y);
            p2_merge(c.x, c.y, d.x, d.y);
            p2_merge(a.x, a.y, c.x, c.y);
            int cb = (2 * (q - 1) + half) * 64;
            t4_insert(pv, pj, a.x, cb + (__float_as_int(a.x) & 0x7F));
            t4_insert(pv, pj, a.y, cb + (__float_as_int(a.y) & 0x7F));
        }

        // wait for this epoch's B tile
        MBAR_WAIT(sb + SM_MBAR + 8 + (uint32_t)(half * 2 + buf) * 8, (q >> 1) & 1);

        float acc[2][4][4];
#pragma unroll
        for (int mt = 0; mt < 2; mt++)
#pragma unroll
            for (int nt = 0; nt < 4; nt++)
#pragma unroll
                for (int e = 0; e < 4; e++) acc[mt][nt][e] = 0.0f;

        const uint32_t bbase = bbase0 + (uint32_t)buf * 32768;
#pragma unroll
        for (int t16 = 0; t16 < 16; t16++) {
            const uint32_t g = (uint32_t)((t16 >> 2) << 7);
            uint32_t ba = bbase + g + boff[t16 & 3];
            uint32_t q0[4], q1[4];
            ldsm_x4(q0, ba);
            ldsm_x4(q1, ba + 8192);
            uint32_t aa = abase + g + aoff[t16 & 3];
            uint32_t a0[4], a1[4];
            ldsm_x4(a0, aa);
            ldsm_x4(a1, aa + 8192);
            mma16816(acc[0][0], a0, q0);
            mma16816(acc[0][1], a0, q0 + 2);
            mma16816(acc[0][2], a0, q1);
            mma16816(acc[0][3], a0, q1 + 2);
            mma16816(acc[1][0], a1, q0);
            mma16816(acc[1][1], a1, q0 + 2);
            mma16816(acc[1][2], a1, q1);
            mma16816(acc[1][3], a1, q1 + 2);
        }

        // epilogue: packed distances -> min2 tournament -> ONE shfl round ->
        // two lanes per quad write their pair to RED[buf]
        {
            const int tile = 2 * q + half;
            float enx[4], eny[4];
#pragma unroll
            for (int nt = 0; nt < 4; nt++) {
                float2 en = __ldg((const float2*)&g_enorm[tile * 64 + lc0 + nt * 8]);
                enx[nt] = en.x;   // +512 pre-folded into g_enorm
                eny[nt] = en.y;
            }
#pragma unroll
            for (int mt = 0; mt < 2; mt++) {
#pragma unroll
                for (int h = 0; h < 2; h++) {
                    float p[8];
#pragma unroll
                    for (int nt = 0; nt < 4; nt++) {
                        uint32_t lc = lc0 + nt * 8;
                        p[2 * nt]     = pack7(fmaf(-2.0f, acc[mt][nt][h * 2],     enx[nt]), lc);
                        p[2 * nt + 1] = pack7(fmaf(-2.0f, acc[mt][nt][h * 2 + 1], eny[nt]), lc + 1);
                    }
                    float l0 = fminf(p[0], p[1]), h0 = fmaxf(p[0], p[1]);
                    float l1 = fminf(p[2], p[3]), h1 = fmaxf(p[2], p[3]);
                    float l2 = fminf(p[4], p[5]), h2 = fmaxf(p[4], p[5]);
                    float l3 = fminf(p[6], p[7]), h3 = fmaxf(p[6], p[7]);
                    p2_merge(l0, h0, l1, h1);
                    p2_merge(l2, h2, l3, h3);
                    p2_merge(l0, h0, l2, h2);
                    {
                        float fl = __shfl_xor_sync(0xffffffffu, l0, 1);
                        float fh = __shfl_xor_sync(0xffffffffu, h0, 1);
                        p2_merge(l0, h0, fl, fh);
                    }
                    if ((l & 1) == 0) {
                        int rl = wm * 32 + mt * 16 + h * 8 + (l >> 2);
                        int pr = (l >> 1) & 1;
                        ((float2*)(smem + (redb - sb) + buf * 5120))[rl * 5 + wn * 2 + pr] =
                            make_float2(l0, h0);
                    }
                }
            }
        }
    }

    bar_sync(half + 1);
    // merge last tile (q=63, buf=1)
    if (htid < 128) {
        const float2* src = (const float2*)(smem + (redb - sb) + 5120) + htid * 5;
        float2 a = src[0], b = src[1], c = src[2], d = src[3];
        p2_merge(a.x, a.y, b.x, b.y);
        p2_merge(c.x, c.y, d.x, d.y);
        p2_merge(a.x, a.y, c.x, c.y);
        int cb = (2 * 63 + half) * 64;
        t4_insert(pv, pj, a.x, cb + (__float_as_int(a.x) & 0x7F));
        t4_insert(pv, pj, a.y, cb + (__float_as_int(a.y) & 0x7F));
    }
    // half 1 publishes its top-4 (values + codes)
    if (half == 1 && htid < 128) {
        float4* cnd = (float4*)(smem + SM_CAND);
        cnd[htid]       = make_float4(pv[0], pv[1], pv[2], pv[3]);
        cnd[128 + htid] = make_float4(__int_as_float(pj[0]), __int_as_float(pj[1]),
                                      __int_as_float(pj[2]), __int_as_float(pj[3]));
    }
    __syncthreads();
    // half 0's first 128 threads union-merge -> global top-4 -> final cand
    if (tid < 128) {
        const float4* cnd = (const float4*)(smem + SM_CAND);
        float4 f = cnd[tid], ii = cnd[128 + tid];
        t4_insert(pv, pj, f.x, __float_as_int(ii.x));
        t4_insert(pv, pj, f.y, __float_as_int(ii.y));
        t4_insert(pv, pj, f.z, __float_as_int(ii.z));
        t4_insert(pv, pj, f.w, __float_as_int(ii.w));
        ((int4*)(smem + SM_CAND))[tid] = make_int4(pj[0], pj[1], pj[2], pj[3]);
    }
    __syncthreads();

    // ---- fused gather: 16 warps x 8 rows; lane owns d in [l*8, l*8+8).
    //      exact fp32 rescore; quantize/diff; red.v4 scatter into g_avgT ----
    float ssacc = 0.0f;
#pragma unroll 1
    for (int rr = 0; rr < 8; rr++) {
        const int rl = wid * 8 + rr;
        const int r  = row0 + rl;
        const int4 cand = ((const int4*)(smem + SM_CAND))[rl];
        const int cj[4] = {cand.x, cand.y, cand.z, cand.w};

        float4 zva = *(const float4*)(z + (size_t)r * DIMS + l * 8);
        float4 zvb = *(const float4*)(z + (size_t)r * DIMS + l * 8 + 4);

        float dot[4];
#pragma unroll
        for (int c = 0; c < 4; c++) {
            const float* e = g_eT + (size_t)cj[c] * DIMS + l * 8;
            float4 ea = *(const float4*)e, eb = *(const float4*)(e + 4);
            float s = zva.x * ea.x;
            s = fmaf(zva.y, ea.y, s); s = fmaf(zva.z, ea.z, s);
            s = fmaf(zva.w, ea.w, s); s = fmaf(zvb.x, eb.x, s);
            s = fmaf(zvb.y, eb.y, s); s = fmaf(zvb.z, eb.z, s);
            s = fmaf(zvb.w, eb.w, s);
            dot[c] = s;
        }
#pragma unroll
        for (int c = 0; c < 4; c++)
#pragma unroll
            for (int o = 16; o; o >>= 1) dot[c] += __shfl_xor_sync(0xffffffffu, dot[c], o);

        int bj = cj[0];
        float bd = fmaf(-2.0f, dot[0], g_enorm[cj[0]]);
#pragma unroll
        for (int c = 1; c < 4; c++) {
            float d = fmaf(-2.0f, dot[c], g_enorm[cj[c]]);
            if (d < bd || (d == bd && cj[c] < bj)) { bd = d; bj = cj[c]; }
        }

        const float* eb = g_eT + (size_t)bj * DIMS + l * 8;
        float4 ea = *(const float4*)eb, eb4 = *(const float4*)(eb + 4);
        *(float4*)(out + OFF_Q + (size_t)r * DIMS + l * 8)     = ea;
        *(float4*)(out + OFF_Q + (size_t)r * DIMS + l * 8 + 4) = eb4;
        float ss;
        {
            float d0 = ea.x - zva.x, d1 = ea.y - zva.y, d2 = ea.z - zva.z, d3 = ea.w - zva.w;
            float d4 = eb4.x - zvb.x, d5 = eb4.y - zvb.y, d6 = eb4.z - zvb.z, d7 = eb4.w - zvb.w;
            ss = d0 * d0;
            ss = fmaf(d1, d1, ss); ss = fmaf(d2, d2, ss); ss = fmaf(d3, d3, ss);
            ss = fmaf(d4, d4, ss); ss = fmaf(d5, d5, ss); ss = fmaf(d6, d6, ss);
            ss = fmaf(d7, d7, ss);
        }
        float* avgp = g_avgT + (size_t)bj * DIMS + l * 8;
        red_add_v4(avgp,     make_float4(0.01f * zva.x, 0.01f * zva.y,
                                         0.01f * zva.z, 0.01f * zva.w));
        red_add_v4(avgp + 4, make_float4(0.01f * zvb.x, 0.01f * zvb.y,
                                         0.01f * zvb.z, 0.01f * zvb.w));
        if (l == 0) {
            atomicAdd(&g_count[bj], 1);
            out[OFF_IND + r] = (float)bj;
        }
#pragma unroll
        for (int o = 16; o; o >>= 1) ss += __shfl_down_sync(0xffffffffu, ss, o);
        if (l == 0) ssacc += ss;
    }
    if (l == 0) atomicAdd(&out[OFF_DIFF], ssacc);

    // ---- last-CTA tail: new_cluster_size, n, diff scaling ----
    __threadfence();
    __syncthreads();
    int* flag = (int*)(smem + SM_CAND + 4096);
    if (tid == 0) *flag = (atomicAdd(&g_done, 1) == gridDim.x - 1) ? 1 : 0;
    __syncthreads();
    if (*flag) {
        float part = 0.0f;
#pragma unroll
        for (int t = 0; t < NEMB / 512; t++) {
            int j = tid + t * 512;
            float v = fmaf(0.01f, (float)g_count[j], 0.99f * cs[j]);
            out[OFF_NCS + j] = v;
            part += v;
        }
#pragma unroll
        for (int o = 16; o; o >>= 1) part += __shfl_xor_sync(0xffffffffu, part, o);
        float* ws = (float*)(smem + SM_CAND);
        if (l == 0) ws[wid] = part;
        __syncthreads();
        if (tid == 0) {
            float n = 0.0f;
#pragma unroll
            for (int w = 0; w < 16; w++) n += ws[w];
            g_n = n;
            out[OFF_DIFF] *= (1.0f / 4194304.0f);
        }
    }
}

// ---------------------------------------------------------------------------
// F: tiled transpose finalize: AVG[d][j] = 0.99*eavg[d][j] + g_avgT[j][d];
//    EMB = AVG / smoothed(j). block (32,8), 32x32 tiles.
// ---------------------------------------------------------------------------
__global__ void k_final(const float* __restrict__ eavg, float* __restrict__ out) {
    __shared__ float t[32][33];
    int j0 = blockIdx.x * 32, d0 = blockIdx.y * 32;
    int tx = threadIdx.x, ty = threadIdx.y;
#pragma unroll
    for (int s = 0; s < 32; s += 8)
        t[ty + s][tx] = g_avgT[(size_t)(j0 + ty + s) * DIMS + d0 + tx];
    __syncthreads();
    float n = g_n;
    int j = j0 + tx;
    float ncs = out[OFF_NCS + j];
    float inv_smoothed = (n + (float)NEMB * 1e-5f) / ((ncs + 1e-5f) * n);
#pragma unroll
    for (int s = 0; s < 32; s += 8) {
        int d = d0 + ty + s;
        size_t o = (size_t)d * NEMB + j;
        float avg = fmaf(0.99f, eavg[o], t[tx][ty + s]);
        out[OFF_AVG + o] = avg;
        out[OFF_EMB + o] = avg * inv_smoothed;
    }
}

// ---------------------------------------------------------------------------
extern "C" void kernel_launch(void* const* d_in, const int* in_sizes, int n_in,
                              void* d_out, int out_size) {
    const float* z    = (const float*)d_in[0];   // [16,32,32,256]
    const float* E    = (const float*)d_in[1];   // [256, 8192]
    const float* cs   = (const float*)d_in[2];   // [8192]
    const float* eavg = (const float*)d_in[3];   // [256, 8192]
    float* out = (float*)d_out;

    static int cfg_done = 0;
    if (!cfg_done) {
        cudaFuncSetAttribute(k_argmin_mma,
                             cudaFuncAttributeMaxDynamicSharedMemorySize, SMEM_TOTAL);
        cfg_done = 1;
    }

    {
        dim3 b(32, 8);
        k_prep_all<<<CONV_BLOCKS + PREP_BLOCKS, b>>>(z, E, out);
    }
    k_argmin_mma<<<NROWS / 128, 512, SMEM_TOTAL>>>(z, cs, out);
    {
        dim3 g(NEMB / 32, DIMS / 32), b(32, 8);
        k_final<<<g, b>>>(eavg, out);
    }
}